// round 10
// baseline (speedup 1.0000x reference)
#include <cuda_runtime.h>

// Problem constants (fixed by dataset)
#define NIMG 8
#define NCLS 21
#define NPIX 262144      // 512*512 = 2^18
#define NDIM 32
#define IGNORE_LAB 255
#define PSHIFT 18

// Scratch (__device__ globals; finalize re-zeroes them each call; initial
// state is zero from static init -> every call starts from zeros)
__device__ float        g_sums[NIMG * NCLS * NDIM];
__device__ float        g_counts[NIMG * NCLS];
__device__ double       g_scal[5];     // 0:ce 1:validcnt 2:var 3:inter 4:sumsq
__device__ unsigned int g_ctr;

// ---------------------------------------------------------------------------
// Kernel 1: logit pass (unchanged from R9 — runs at ~5.9 TB/s).
// ---------------------------------------------------------------------------
__global__ __launch_bounds__(256) void k_logit(const float* __restrict__ logit,
                                               const int* __restrict__ target) {
    int tid = blockIdx.x * blockDim.x + threadIdx.x;
    int stride = gridDim.x * blockDim.x;

    float ce = 0.f, cnt = 0.f, var = 0.f, inter = 0.f;

    for (int g = tid; g < NIMG * NPIX; g += stride) {
        int n = g >> PSHIFT;
        int p = g & (NPIX - 1);
        const float* lp = logit + (size_t)n * NCLS * NPIX + p;

        float v[NCLS];
#pragma unroll
        for (int c = 0; c < NCLS; c++) v[c] = __ldcs(lp + (size_t)c * NPIX);

        float m = v[0];
#pragma unroll
        for (int c = 1; c < NCLS; c++) m = fmaxf(m, v[c]);

        float s = 0.f, tot = 0.f;
#pragma unroll
        for (int c = 0; c < NCLS; c++) {
            s += __expf(v[c] - m);
            tot += v[c];
        }
        float lse = m + __logf(s);

        int lab = __ldg(target + g);
        if (lab != IGNORE_LAB) {
            float lg = v[0];
#pragma unroll
            for (int c = 1; c < NCLS; c++) lg = (c == lab) ? v[c] : lg;
            ce += (lse - lg);
            cnt += 1.f;
            var -= lg;
            inter += (tot - lg);
        }
    }

    int lane = threadIdx.x & 31;
    int wid = threadIdx.x >> 5;
#pragma unroll
    for (int o = 16; o > 0; o >>= 1) {
        ce += __shfl_down_sync(0xffffffffu, ce, o);
        cnt += __shfl_down_sync(0xffffffffu, cnt, o);
        var += __shfl_down_sync(0xffffffffu, var, o);
        inter += __shfl_down_sync(0xffffffffu, inter, o);
    }
    __shared__ float sred[4][8];
    if (lane == 0) {
        sred[0][wid] = ce; sred[1][wid] = cnt; sred[2][wid] = var; sred[3][wid] = inter;
    }
    __syncthreads();
    if (threadIdx.x == 0) {
        float a = 0, b = 0, c2 = 0, d2 = 0;
#pragma unroll
        for (int w = 0; w < 8; w++) {
            a += sred[0][w]; b += sred[1][w]; c2 += sred[2][w]; d2 += sred[3][w];
        }
        atomicAdd(&g_scal[0], (double)a);
        atomicAdd(&g_scal[1], (double)b);
        atomicAdd(&g_scal[2], (double)c2);
        atomicAdd(&g_scal[3], (double)d2);
    }
}

// ---------------------------------------------------------------------------
// Kernel 2: feature pass, restructured hot loop:
//   - counts accumulated in REGISTERS (lane c counts label==c) -> zero count
//     smem RMWs in the loop
//   - labels loaded as int4 (one uniform LDG.128 per 4 labels)
//   - 8-pixel unroll for MLP=8 on the feature stream
// Plus last-block finalize + scratch re-zero (proven in R8/R9).
// ---------------------------------------------------------------------------
#define BLOCKS_PER_IMG 128
#define FEAT_GRID (BLOCKS_PER_IMG * NIMG)      // 1024
#define WARPS_PER_BLK 8
#define PIX_PER_WARP (NPIX / (BLOCKS_PER_IMG * WARPS_PER_BLK))   // 256

__global__ __launch_bounds__(256) void k_feat(const float* __restrict__ feat,
                                              const int* __restrict__ target,
                                              float* __restrict__ out) {
    __shared__ float acc[WARPS_PER_BLK][NCLS * NDIM];  // 21504 B
    __shared__ int   cshi[WARPS_PER_BLK][32];          // per-warp reg-count dump
    __shared__ float sq[WARPS_PER_BLK];
    __shared__ double dred[256];
    __shared__ bool is_last;

    const int lane = threadIdx.x & 31;
    const int wid = threadIdx.x >> 5;
    const int n = blockIdx.y;

    for (int idx = threadIdx.x; idx < WARPS_PER_BLK * NCLS * NDIM; idx += blockDim.x)
        (&acc[0][0])[idx] = 0.f;
    __syncthreads();

    const int p0 = (blockIdx.x * WARPS_PER_BLK + wid) * PIX_PER_WARP;
    const int* tg = target + (size_t)n * NPIX;
    const float* fp = feat + (size_t)n * NPIX * NDIM;

    float ssq = 0.f;
    int cntreg = 0;                 // lane c holds count of class c (c = lane id)
    float* myacc = &acc[wid][0];

#pragma unroll 1
    for (int p = p0; p < p0 + PIX_PER_WARP; p += 8) {
        // labels: two uniform 16B loads cover 8 pixels
        int4 la = __ldg((const int4*)(tg + p));
        int4 lb = __ldg((const int4*)(tg + p + 4));
        int lab[8] = { la.x, la.y, la.z, la.w, lb.x, lb.y, lb.z, lb.w };

        // batch 8 feature loads (MLP=8)
        float f[8];
#pragma unroll
        for (int j = 0; j < 8; j++)
            f[j] = __ldcs(fp + (size_t)(p + j) * NDIM + lane);

#pragma unroll
        for (int j = 0; j < 8; j++) {
            int l = lab[j];
            cntreg += (l == lane) ? 1 : 0;       // register count, no smem
            if (l != IGNORE_LAB) {
                myacc[l * NDIM + lane] += f[j];
                ssq += f[j] * f[j];
            }
        }
    }
    __syncthreads();

    // combine 8 warp buffers -> global partials
    for (int idx = threadIdx.x; idx < NCLS * NDIM; idx += blockDim.x) {
        float s = 0.f;
#pragma unroll
        for (int w = 0; w < WARPS_PER_BLK; w++) s += acc[w][idx];
        atomicAdd(&g_sums[(size_t)n * NCLS * NDIM + idx], s);
    }

    // counts: dump per-warp register counts, sum across warps
    cshi[wid][lane] = cntreg;
#pragma unroll
    for (int o = 16; o > 0; o >>= 1) ssq += __shfl_down_sync(0xffffffffu, ssq, o);
    if (lane == 0) sq[wid] = ssq;
    __syncthreads();

    if (threadIdx.x < NCLS) {
        int s = 0;
#pragma unroll
        for (int w = 0; w < WARPS_PER_BLK; w++) s += cshi[w][threadIdx.x];
        atomicAdd(&g_counts[n * NCLS + threadIdx.x], (float)s);
    }
    if (threadIdx.x == 0) {
        float s = 0.f;
#pragma unroll
        for (int w = 0; w < WARPS_PER_BLK; w++) s += sq[w];
        atomicAdd(&g_scal[4], (double)s);
    }

    // ---------------- last-block finalize + re-zero ----------------------
    __threadfence();
    if (threadIdx.x == 0)
        is_last = (atomicAdd(&g_ctr, 1u) == FEAT_GRID - 1);
    __syncthreads();
    if (!is_last) return;
    __threadfence();   // acquire: all other blocks' atomics visible

    int tid = threadIdx.x;
    double center_neg = 0.0;
    for (int i = tid; i < NIMG * NCLS; i += 256) {
        double cntv = (double)__ldcg(&g_counts[i]);
        if (cntv > 0.0) {
            double m2 = 0.0;
            const float* s = &g_sums[(size_t)i * NDIM];
#pragma unroll
            for (int d = 0; d < NDIM; d++) {
                double sv = (double)__ldcg(s + d);
                m2 += sv * sv;
            }
            center_neg -= m2 / cntv;
        }
    }
    dred[tid] = center_neg;
    __syncthreads();
    for (int o = 128; o > 0; o >>= 1) {
        if (tid < o) dred[tid] += dred[tid + o];
        __syncthreads();
    }
    if (tid == 0) {
        double s0 = __ldcg(&g_scal[0]), s1 = __ldcg(&g_scal[1]);
        double s2 = __ldcg(&g_scal[2]), s3 = __ldcg(&g_scal[3]);
        double s4 = __ldcg(&g_scal[4]);
        double denom = s1 > 1.0 ? s1 : 1.0;
        double CE = s0 / denom;
        double VAR = s2 / (double)NPIX;
        double Inter = s3 / (double)NPIX;
        double Center = (s4 + dred[0]) / (double)NPIX;
        double loss = (CE + 1.0 * VAR + 0.5 * Inter + 0.1 * Center) / (double)NIMG;
        out[0] = (float)loss;
    }
    __syncthreads();   // all scratch reads complete before re-zero

    for (int i = tid; i < NIMG * NCLS * NDIM; i += 256) g_sums[i] = 0.f;
    if (tid < NIMG * NCLS) g_counts[tid] = 0.f;
    if (tid < 5) g_scal[tid] = 0.0;
    if (tid == 0) g_ctr = 0u;
}

// ---------------------------------------------------------------------------
extern "C" void kernel_launch(void* const* d_in, const int* in_sizes, int n_in,
                              void* d_out, int out_size) {
    const float* logit = (const float*)d_in[0];
    const int* target = (const int*)d_in[1];
    const float* feat = (const float*)d_in[2];
    float* out = (float*)d_out;

    k_logit<<<1184, 256>>>(logit, target);
    k_feat<<<dim3(BLOCKS_PER_IMG, NIMG), 256>>>(feat, target, out);
}

// round 11
// speedup vs baseline: 1.1453x; 1.1453x over previous
#include <cuda_runtime.h>

// Problem constants (fixed by dataset)
#define NIMG 8
#define NCLS 21
#define NPIX 262144      // 512*512 = 2^18
#define NDIM 32
#define IGNORE_LAB 255
#define PSHIFT 18

// Scratch (__device__ globals; finalize re-zeroes them each call; initial
// state is zero from static init -> every call starts from zeros)
__device__ float        g_sums[NIMG * NCLS * NDIM];
__device__ float        g_counts[NIMG * NCLS];
__device__ double       g_scal[5];     // 0:ce 1:validcnt 2:var 3:inter 4:sumsq
__device__ unsigned int g_ctr;

// ---------------------------------------------------------------------------
// Kernel 1: logit pass (unchanged — runs at ~5.9 TB/s effective).
// ---------------------------------------------------------------------------
__global__ __launch_bounds__(256) void k_logit(const float* __restrict__ logit,
                                               const int* __restrict__ target) {
    int tid = blockIdx.x * blockDim.x + threadIdx.x;
    int stride = gridDim.x * blockDim.x;

    float ce = 0.f, cnt = 0.f, var = 0.f, inter = 0.f;

    for (int g = tid; g < NIMG * NPIX; g += stride) {
        int n = g >> PSHIFT;
        int p = g & (NPIX - 1);
        const float* lp = logit + (size_t)n * NCLS * NPIX + p;

        float v[NCLS];
#pragma unroll
        for (int c = 0; c < NCLS; c++) v[c] = __ldcs(lp + (size_t)c * NPIX);

        float m = v[0];
#pragma unroll
        for (int c = 1; c < NCLS; c++) m = fmaxf(m, v[c]);

        float s = 0.f, tot = 0.f;
#pragma unroll
        for (int c = 0; c < NCLS; c++) {
            s += __expf(v[c] - m);
            tot += v[c];
        }
        float lse = m + __logf(s);

        int lab = __ldg(target + g);
        if (lab != IGNORE_LAB) {
            float lg = v[0];
#pragma unroll
            for (int c = 1; c < NCLS; c++) lg = (c == lab) ? v[c] : lg;
            ce += (lse - lg);
            cnt += 1.f;
            var -= lg;
            inter += (tot - lg);
        }
    }

    int lane = threadIdx.x & 31;
    int wid = threadIdx.x >> 5;
#pragma unroll
    for (int o = 16; o > 0; o >>= 1) {
        ce += __shfl_down_sync(0xffffffffu, ce, o);
        cnt += __shfl_down_sync(0xffffffffu, cnt, o);
        var += __shfl_down_sync(0xffffffffu, var, o);
        inter += __shfl_down_sync(0xffffffffu, inter, o);
    }
    __shared__ float sred[4][8];
    if (lane == 0) {
        sred[0][wid] = ce; sred[1][wid] = cnt; sred[2][wid] = var; sred[3][wid] = inter;
    }
    __syncthreads();
    if (threadIdx.x == 0) {
        float a = 0, b = 0, c2 = 0, d2 = 0;
#pragma unroll
        for (int w = 0; w < 8; w++) {
            a += sred[0][w]; b += sred[1][w]; c2 += sred[2][w]; d2 += sred[3][w];
        }
        atomicAdd(&g_scal[0], (double)a);
        atomicAdd(&g_scal[1], (double)b);
        atomicAdd(&g_scal[2], (double)c2);
        atomicAdd(&g_scal[3], (double)d2);
    }
}

// ---------------------------------------------------------------------------
// Kernel 2: feature pass — exact R9 structure (4 named scalar loads, proven
// MLP=4, 80.9us) with ONE change: counts in registers (lane c counts
// label==c), removing all count smem RMWs and the lane==0 path from the loop.
// Plus last-block finalize + scratch re-zero (proven).
// ---------------------------------------------------------------------------
#define BLOCKS_PER_IMG 128
#define FEAT_GRID (BLOCKS_PER_IMG * NIMG)      // 1024
#define WARPS_PER_BLK 8
#define PIX_PER_WARP (NPIX / (BLOCKS_PER_IMG * WARPS_PER_BLK))   // 256

__global__ __launch_bounds__(256) void k_feat(const float* __restrict__ feat,
                                              const int* __restrict__ target,
                                              float* __restrict__ out) {
    __shared__ float acc[WARPS_PER_BLK][NCLS * NDIM];  // 21504 B
    __shared__ int   cshi[WARPS_PER_BLK][32];          // per-warp reg-count dump
    __shared__ float sq[WARPS_PER_BLK];
    __shared__ double dred[256];
    __shared__ bool is_last;

    const int lane = threadIdx.x & 31;
    const int wid = threadIdx.x >> 5;
    const int n = blockIdx.y;

    for (int idx = threadIdx.x; idx < WARPS_PER_BLK * NCLS * NDIM; idx += blockDim.x)
        (&acc[0][0])[idx] = 0.f;
    __syncthreads();

    const int p0 = (blockIdx.x * WARPS_PER_BLK + wid) * PIX_PER_WARP;
    const int* tg = target + (size_t)n * NPIX;
    const float* fp = feat + (size_t)n * NPIX * NDIM;

    float ssq = 0.f;
    int cntreg = 0;                 // lane c holds count of class c
    float* myacc = &acc[wid][0];

#pragma unroll 1
    for (int p = p0; p < p0 + PIX_PER_WARP; p += 4) {
        // named scalar loads -> ptxas front-batches these (proven in R9)
        int l0 = __ldg(tg + p + 0), l1 = __ldg(tg + p + 1);
        int l2 = __ldg(tg + p + 2), l3 = __ldg(tg + p + 3);
        float f0 = __ldcs(fp + (size_t)(p + 0) * NDIM + lane);
        float f1 = __ldcs(fp + (size_t)(p + 1) * NDIM + lane);
        float f2 = __ldcs(fp + (size_t)(p + 2) * NDIM + lane);
        float f3 = __ldcs(fp + (size_t)(p + 3) * NDIM + lane);

        cntreg += (l0 == lane) ? 1 : 0;
        cntreg += (l1 == lane) ? 1 : 0;
        cntreg += (l2 == lane) ? 1 : 0;
        cntreg += (l3 == lane) ? 1 : 0;

        if (l0 != IGNORE_LAB) { myacc[l0 * NDIM + lane] += f0; ssq += f0 * f0; }
        if (l1 != IGNORE_LAB) { myacc[l1 * NDIM + lane] += f1; ssq += f1 * f1; }
        if (l2 != IGNORE_LAB) { myacc[l2 * NDIM + lane] += f2; ssq += f2 * f2; }
        if (l3 != IGNORE_LAB) { myacc[l3 * NDIM + lane] += f3; ssq += f3 * f3; }
    }
    __syncthreads();

    // combine 8 warp buffers -> global partials
    for (int idx = threadIdx.x; idx < NCLS * NDIM; idx += blockDim.x) {
        float s = 0.f;
#pragma unroll
        for (int w = 0; w < WARPS_PER_BLK; w++) s += acc[w][idx];
        atomicAdd(&g_sums[(size_t)n * NCLS * NDIM + idx], s);
    }

    // counts: dump per-warp register counts, sum across warps
    cshi[wid][lane] = cntreg;
#pragma unroll
    for (int o = 16; o > 0; o >>= 1) ssq += __shfl_down_sync(0xffffffffu, ssq, o);
    if (lane == 0) sq[wid] = ssq;
    __syncthreads();

    if (threadIdx.x < NCLS) {
        int s = 0;
#pragma unroll
        for (int w = 0; w < WARPS_PER_BLK; w++) s += cshi[w][threadIdx.x];
        atomicAdd(&g_counts[n * NCLS + threadIdx.x], (float)s);
    }
    if (threadIdx.x == 0) {
        float s = 0.f;
#pragma unroll
        for (int w = 0; w < WARPS_PER_BLK; w++) s += sq[w];
        atomicAdd(&g_scal[4], (double)s);
    }

    // ---------------- last-block finalize + re-zero ----------------------
    __threadfence();
    if (threadIdx.x == 0)
        is_last = (atomicAdd(&g_ctr, 1u) == FEAT_GRID - 1);
    __syncthreads();
    if (!is_last) return;
    __threadfence();   // acquire: all other blocks' atomics visible

    int tid = threadIdx.x;
    double center_neg = 0.0;
    for (int i = tid; i < NIMG * NCLS; i += 256) {
        double cntv = (double)__ldcg(&g_counts[i]);
        if (cntv > 0.0) {
            double m2 = 0.0;
            const float* s = &g_sums[(size_t)i * NDIM];
#pragma unroll
            for (int d = 0; d < NDIM; d++) {
                double sv = (double)__ldcg(s + d);
                m2 += sv * sv;
            }
            center_neg -= m2 / cntv;
        }
    }
    dred[tid] = center_neg;
    __syncthreads();
    for (int o = 128; o > 0; o >>= 1) {
        if (tid < o) dred[tid] += dred[tid + o];
        __syncthreads();
    }
    if (tid == 0) {
        double s0 = __ldcg(&g_scal[0]), s1 = __ldcg(&g_scal[1]);
        double s2 = __ldcg(&g_scal[2]), s3 = __ldcg(&g_scal[3]);
        double s4 = __ldcg(&g_scal[4]);
        double denom = s1 > 1.0 ? s1 : 1.0;
        double CE = s0 / denom;
        double VAR = s2 / (double)NPIX;
        double Inter = s3 / (double)NPIX;
        double Center = (s4 + dred[0]) / (double)NPIX;
        double loss = (CE + 1.0 * VAR + 0.5 * Inter + 0.1 * Center) / (double)NIMG;
        out[0] = (float)loss;
    }
    __syncthreads();   // all scratch reads complete before re-zero

    for (int i = tid; i < NIMG * NCLS * NDIM; i += 256) g_sums[i] = 0.f;
    if (tid < NIMG * NCLS) g_counts[tid] = 0.f;
    if (tid < 5) g_scal[tid] = 0.0;
    if (tid == 0) g_ctr = 0u;
}

// ---------------------------------------------------------------------------
extern "C" void kernel_launch(void* const* d_in, const int* in_sizes, int n_in,
                              void* d_out, int out_size) {
    const float* logit = (const float*)d_in[0];
    const int* target = (const int*)d_in[1];
    const float* feat = (const float*)d_in[2];
    float* out = (float*)d_out;

    k_logit<<<1184, 256>>>(logit, target);
    k_feat<<<dim3(BLOCKS_PER_IMG, NIMG), 256>>>(feat, target, out);
}

// round 12
// speedup vs baseline: 1.3795x; 1.2045x over previous
#include <cuda_runtime.h>

// Problem constants (fixed by dataset)
#define NIMG 8
#define NCLS 21
#define NCLS_PAD 22          // row 21 = trash row for IGNORE pixels
#define NPIX 262144          // 512*512 = 2^18
#define NDIM 32
#define IGNORE_LAB 255
#define PSHIFT 18

// Scratch (__device__ globals; finalize re-zeroes them each call; initial
// state is zero from static init -> every call starts from zeros)
__device__ float        g_sums[NIMG * NCLS * NDIM];
__device__ float        g_counts[NIMG * NCLS];
__device__ double       g_scal[5];     // 0:ce 1:validcnt 2:var 3:inter 4:sumsq
__device__ unsigned int g_ctr;

// ---------------------------------------------------------------------------
// Kernel 1: logit pass (unchanged — ~28us, near bandwidth roofline).
// ---------------------------------------------------------------------------
__global__ __launch_bounds__(256) void k_logit(const float* __restrict__ logit,
                                               const int* __restrict__ target) {
    int tid = blockIdx.x * blockDim.x + threadIdx.x;
    int stride = gridDim.x * blockDim.x;

    float ce = 0.f, cnt = 0.f, var = 0.f, inter = 0.f;

    for (int g = tid; g < NIMG * NPIX; g += stride) {
        int n = g >> PSHIFT;
        int p = g & (NPIX - 1);
        const float* lp = logit + (size_t)n * NCLS * NPIX + p;

        float v[NCLS];
#pragma unroll
        for (int c = 0; c < NCLS; c++) v[c] = __ldcs(lp + (size_t)c * NPIX);

        float m = v[0];
#pragma unroll
        for (int c = 1; c < NCLS; c++) m = fmaxf(m, v[c]);

        float s = 0.f, tot = 0.f;
#pragma unroll
        for (int c = 0; c < NCLS; c++) {
            s += __expf(v[c] - m);
            tot += v[c];
        }
        float lse = m + __logf(s);

        int lab = __ldg(target + g);
        if (lab != IGNORE_LAB) {
            float lg = v[0];
#pragma unroll
            for (int c = 1; c < NCLS; c++) lg = (c == lab) ? v[c] : lg;
            ce += (lse - lg);
            cnt += 1.f;
            var -= lg;
            inter += (tot - lg);
        }
    }

    int lane = threadIdx.x & 31;
    int wid = threadIdx.x >> 5;
#pragma unroll
    for (int o = 16; o > 0; o >>= 1) {
        ce += __shfl_down_sync(0xffffffffu, ce, o);
        cnt += __shfl_down_sync(0xffffffffu, cnt, o);
        var += __shfl_down_sync(0xffffffffu, var, o);
        inter += __shfl_down_sync(0xffffffffu, inter, o);
    }
    __shared__ float sred[4][8];
    if (lane == 0) {
        sred[0][wid] = ce; sred[1][wid] = cnt; sred[2][wid] = var; sred[3][wid] = inter;
    }
    __syncthreads();
    if (threadIdx.x == 0) {
        float a = 0, b = 0, c2 = 0, d2 = 0;
#pragma unroll
        for (int w = 0; w < 8; w++) {
            a += sred[0][w]; b += sred[1][w]; c2 += sred[2][w]; d2 += sred[3][w];
        }
        atomicAdd(&g_scal[0], (double)a);
        atomicAdd(&g_scal[1], (double)b);
        atomicAdd(&g_scal[2], (double)c2);
        atomicAdd(&g_scal[3], (double)d2);
    }
}

// ---------------------------------------------------------------------------
// Kernel 2: feature pass — BRANCHLESS hot loop.
//   - IGNORE pixels routed to trash row 21 (exact semantics, zero branches)
//   - masked value fm feeds both accumulate and ssq
//   - counts in registers (lane c counts label==c)
//   - 4 named scalar loads (proven front-batched form)
// Plus last-block finalize + scratch re-zero (proven).
// ---------------------------------------------------------------------------
#define BLOCKS_PER_IMG 128
#define FEAT_GRID (BLOCKS_PER_IMG * NIMG)      // 1024
#define WARPS_PER_BLK 8
#define PIX_PER_WARP (NPIX / (BLOCKS_PER_IMG * WARPS_PER_BLK))   // 256

__global__ __launch_bounds__(256) void k_feat(const float* __restrict__ feat,
                                              const int* __restrict__ target,
                                              float* __restrict__ out) {
    __shared__ float acc[WARPS_PER_BLK][NCLS_PAD * NDIM];  // 22528 B
    __shared__ int   cshi[WARPS_PER_BLK][32];
    __shared__ float sq[WARPS_PER_BLK];
    __shared__ double dred[256];
    __shared__ bool is_last;

    const int lane = threadIdx.x & 31;
    const int wid = threadIdx.x >> 5;
    const int n = blockIdx.y;

    for (int idx = threadIdx.x; idx < WARPS_PER_BLK * NCLS_PAD * NDIM; idx += blockDim.x)
        (&acc[0][0])[idx] = 0.f;
    __syncthreads();

    const int p0 = (blockIdx.x * WARPS_PER_BLK + wid) * PIX_PER_WARP;
    const int* tg = target + (size_t)n * NPIX;
    const float* fp = feat + (size_t)n * NPIX * NDIM;

    float ssq = 0.f;
    int cntreg = 0;                 // lane c holds count of class c
    float* myacc = &acc[wid][0];

#pragma unroll 1
    for (int p = p0; p < p0 + PIX_PER_WARP; p += 4) {
        int l0 = __ldg(tg + p + 0), l1 = __ldg(tg + p + 1);
        int l2 = __ldg(tg + p + 2), l3 = __ldg(tg + p + 3);
        float f0 = __ldcs(fp + (size_t)(p + 0) * NDIM + lane);
        float f1 = __ldcs(fp + (size_t)(p + 1) * NDIM + lane);
        float f2 = __ldcs(fp + (size_t)(p + 2) * NDIM + lane);
        float f3 = __ldcs(fp + (size_t)(p + 3) * NDIM + lane);

        // branchless: ignored pixels -> trash row 21, masked value 0
        int  i0 = (l0 != IGNORE_LAB) ? l0 : NCLS;
        int  i1 = (l1 != IGNORE_LAB) ? l1 : NCLS;
        int  i2 = (l2 != IGNORE_LAB) ? l2 : NCLS;
        int  i3 = (l3 != IGNORE_LAB) ? l3 : NCLS;
        float m0 = (l0 != IGNORE_LAB) ? f0 : 0.f;
        float m1 = (l1 != IGNORE_LAB) ? f1 : 0.f;
        float m2 = (l2 != IGNORE_LAB) ? f2 : 0.f;
        float m3 = (l3 != IGNORE_LAB) ? f3 : 0.f;

        cntreg += (l0 == lane) ? 1 : 0;
        cntreg += (l1 == lane) ? 1 : 0;
        cntreg += (l2 == lane) ? 1 : 0;
        cntreg += (l3 == lane) ? 1 : 0;

        myacc[i0 * NDIM + lane] += m0; ssq += m0 * m0;
        myacc[i1 * NDIM + lane] += m1; ssq += m1 * m1;
        myacc[i2 * NDIM + lane] += m2; ssq += m2 * m2;
        myacc[i3 * NDIM + lane] += m3; ssq += m3 * m3;
    }
    __syncthreads();

    // combine 8 warp buffers -> global partials (rows 0..20 only)
    for (int idx = threadIdx.x; idx < NCLS * NDIM; idx += blockDim.x) {
        float s = 0.f;
#pragma unroll
        for (int w = 0; w < WARPS_PER_BLK; w++) s += acc[w][idx];
        atomicAdd(&g_sums[(size_t)n * NCLS * NDIM + idx], s);
    }

    cshi[wid][lane] = cntreg;
#pragma unroll
    for (int o = 16; o > 0; o >>= 1) ssq += __shfl_down_sync(0xffffffffu, ssq, o);
    if (lane == 0) sq[wid] = ssq;
    __syncthreads();

    if (threadIdx.x < NCLS) {
        int s = 0;
#pragma unroll
        for (int w = 0; w < WARPS_PER_BLK; w++) s += cshi[w][threadIdx.x];
        atomicAdd(&g_counts[n * NCLS + threadIdx.x], (float)s);
    }
    if (threadIdx.x == 0) {
        float s = 0.f;
#pragma unroll
        for (int w = 0; w < WARPS_PER_BLK; w++) s += sq[w];
        atomicAdd(&g_scal[4], (double)s);
    }

    // ---------------- last-block finalize + re-zero ----------------------
    __threadfence();
    if (threadIdx.x == 0)
        is_last = (atomicAdd(&g_ctr, 1u) == FEAT_GRID - 1);
    __syncthreads();
    if (!is_last) return;
    __threadfence();   // acquire: all other blocks' atomics visible

    int tid = threadIdx.x;
    double center_neg = 0.0;
    for (int i = tid; i < NIMG * NCLS; i += 256) {
        double cntv = (double)__ldcg(&g_counts[i]);
        if (cntv > 0.0) {
            double m2 = 0.0;
            const float* s = &g_sums[(size_t)i * NDIM];
#pragma unroll
            for (int d = 0; d < NDIM; d++) {
                double sv = (double)__ldcg(s + d);
                m2 += sv * sv;
            }
            center_neg -= m2 / cntv;
        }
    }
    dred[tid] = center_neg;
    __syncthreads();
    for (int o = 128; o > 0; o >>= 1) {
        if (tid < o) dred[tid] += dred[tid + o];
        __syncthreads();
    }
    if (tid == 0) {
        double s0 = __ldcg(&g_scal[0]), s1 = __ldcg(&g_scal[1]);
        double s2 = __ldcg(&g_scal[2]), s3 = __ldcg(&g_scal[3]);
        double s4 = __ldcg(&g_scal[4]);
        double denom = s1 > 1.0 ? s1 : 1.0;
        double CE = s0 / denom;
        double VAR = s2 / (double)NPIX;
        double Inter = s3 / (double)NPIX;
        double Center = (s4 + dred[0]) / (double)NPIX;
        double loss = (CE + 1.0 * VAR + 0.5 * Inter + 0.1 * Center) / (double)NIMG;
        out[0] = (float)loss;
    }
    __syncthreads();   // all scratch reads complete before re-zero

    for (int i = tid; i < NIMG * NCLS * NDIM; i += 256) g_sums[i] = 0.f;
    if (tid < NIMG * NCLS) g_counts[tid] = 0.f;
    if (tid < 5) g_scal[tid] = 0.0;
    if (tid == 0) g_ctr = 0u;
}

// ---------------------------------------------------------------------------
extern "C" void kernel_launch(void* const* d_in, const int* in_sizes, int n_in,
                              void* d_out, int out_size) {
    const float* logit = (const float*)d_in[0];
    const int* target = (const int*)d_in[1];
    const float* feat = (const float*)d_in[2];
    float* out = (float*)d_out;

    k_logit<<<1184, 256>>>(logit, target);
    k_feat<<<dim3(BLOCKS_PER_IMG, NIMG), 256>>>(feat, target, out);
}